// round 1
// baseline (speedup 1.0000x reference)
#include <cuda_runtime.h>
#include <math.h>

// Problem constants
#define B_ 4
#define L_ 2048
#define C_ 1024
#define H_ 16
#define D_ 64
#define M_ (B_ * L_)   // 8192
#define N_ (3 * C_)    // 3072
#define K_ (C_)        // 1024

// Scratch: Q/K/V in [B, H, L, D] layout (each 32 MB)
__device__ float g_q[B_ * H_ * L_ * D_];
__device__ float g_k[B_ * H_ * L_ * D_];
__device__ float g_v[B_ * H_ * L_ * D_];

// ---------------------------------------------------------------------------
// Kernel 1: qkv = x @ Wqkv + bias, scattered into [B,H,L,D] Q/K/V scratch.
// 128x128x16 tile, 256 threads, 8x8 register micro-tile per thread.
// ---------------------------------------------------------------------------
__global__ __launch_bounds__(256) void qkv_gemm_kernel(
    const float* __restrict__ x, const float* __restrict__ W,
    const float* __restrict__ bias)
{
    __shared__ float As[16][128];   // A^T tile: As[k][m]
    __shared__ float Bs[16][128];   // B tile:   Bs[k][n]

    const int tid = threadIdx.x;
    const int m0 = blockIdx.y * 128;
    const int n0 = blockIdx.x * 128;
    const int tm = (tid >> 4) << 3;   // 0..120 step 8
    const int tn = (tid & 15) << 3;   // 0..120 step 8

    float acc[8][8];
#pragma unroll
    for (int i = 0; i < 8; i++)
#pragma unroll
        for (int j = 0; j < 8; j++) acc[i][j] = 0.0f;

    for (int k0 = 0; k0 < K_; k0 += 16) {
#pragma unroll
        for (int it = 0; it < 2; it++) {
            int lin = tid + it * 256;            // 0..511
            // A: 128 rows x 16 cols, float4 along k
            int arow = lin >> 2;                 // 0..127
            int acol = (lin & 3) << 2;           // 0,4,8,12
            float4 a = *reinterpret_cast<const float4*>(
                &x[(m0 + arow) * K_ + k0 + acol]);
            As[acol + 0][arow] = a.x;
            As[acol + 1][arow] = a.y;
            As[acol + 2][arow] = a.z;
            As[acol + 3][arow] = a.w;
            // B: 16 rows x 128 cols, float4 along n
            int brow = lin >> 5;                 // 0..15
            int bcol = (lin & 31) << 2;          // 0..124
            *reinterpret_cast<float4*>(&Bs[brow][bcol]) =
                *reinterpret_cast<const float4*>(&W[(k0 + brow) * N_ + n0 + bcol]);
        }
        __syncthreads();

#pragma unroll
        for (int kk = 0; kk < 16; kk++) {
            float a[8], b[8];
            *reinterpret_cast<float4*>(&a[0]) = *reinterpret_cast<float4*>(&As[kk][tm]);
            *reinterpret_cast<float4*>(&a[4]) = *reinterpret_cast<float4*>(&As[kk][tm + 4]);
            *reinterpret_cast<float4*>(&b[0]) = *reinterpret_cast<float4*>(&Bs[kk][tn]);
            *reinterpret_cast<float4*>(&b[4]) = *reinterpret_cast<float4*>(&Bs[kk][tn + 4]);
#pragma unroll
            for (int i = 0; i < 8; i++)
#pragma unroll
                for (int j = 0; j < 8; j++)
                    acc[i][j] = fmaf(a[i], b[j], acc[i][j]);
        }
        __syncthreads();
    }

    // Epilogue: bias + scatter into [B,H,L,D]. All n in this block share q/k/v.
    const int which = n0 >> 10;  // 0=q, 1=k, 2=v (128 | 1024)
    float* dst = (which == 0) ? g_q : ((which == 1) ? g_k : g_v);
#pragma unroll
    for (int i = 0; i < 8; i++) {
        int m  = m0 + tm + i;
        int bb = m >> 11;            // / L_
        int l  = m & (L_ - 1);
#pragma unroll
        for (int j = 0; j < 8; j++) {
            int n = n0 + tn + j;
            int c = n & (C_ - 1);
            int h = c >> 6;
            int d = c & 63;
            dst[(((bb * H_ + h) * L_ + l) << 6) + d] = acc[i][j] + bias[n];
        }
    }
}

// ---------------------------------------------------------------------------
// Kernel 2: causal flash attention. One block per (b*h, 64-row query tile).
// 64-wide key tiles, online softmax, 4x4 micro-tiles, 256 threads.
// ---------------------------------------------------------------------------
#define SMPAD 65

__global__ __launch_bounds__(256) void attn_kernel(float* __restrict__ y)
{
    extern __shared__ float sm[];
    float* Qt   = sm;                    // [d][i]  64 x 65
    float* Kt   = Qt + 64 * SMPAD;       // [d][j]  64 x 65
    float* Vs   = Kt + 64 * SMPAD;       // [j][d]  64 x 65
    float* Ss   = Vs + 64 * SMPAD;       // [j][i]  64 x 65 (scores, then P)
    float* m_sh = Ss + 64 * SMPAD;       // [64] row max
    float* l_sh = m_sh + 64;             // [64] row sum
    float* al_sh = l_sh + 64;            // [64] rescale factor

    const int bh  = blockIdx.y;          // 0..63  (b*H + h)
    const int qt  = blockIdx.x;          // 0..31  query tile
    const int tid = threadIdx.x;
    const float scale = 0.125f;          // 1/sqrt(64)

    const float* qg = g_q + (bh * L_ + qt * 64) * 64;
    const float* kg = g_k + bh * L_ * 64;
    const float* vg = g_v + bh * L_ * 64;

    // Load Q tile transposed (d-major)
    for (int idx = tid; idx < 4096; idx += 256) {
        int r = idx >> 6, d = idx & 63;
        Qt[d * SMPAD + r] = qg[idx];
    }
    if (tid < 64) { m_sh[tid] = -1e30f; l_sh[tid] = 0.0f; }

    const int ti = (tid >> 4) << 2;      // query rows  [ti, ti+4)
    const int tj = (tid & 15) << 2;      // key cols / d cols [tj, tj+4)

    float O[4][4];
#pragma unroll
    for (int i = 0; i < 4; i++)
#pragma unroll
        for (int j = 0; j < 4; j++) O[i][j] = 0.0f;

    for (int kt = 0; kt <= qt; kt++) {
        __syncthreads();   // protect Kt/Vs/Ss from previous iteration's readers
        for (int idx = tid; idx < 4096; idx += 256) {
            int r = idx >> 6, d = idx & 63;
            float kv = kg[kt * 4096 + idx];
            Kt[d * SMPAD + r] = kv;
            Vs[r * SMPAD + d] = vg[kt * 4096 + idx];
        }
        __syncthreads();

        // S = Q K^T (4x4 micro-tile per thread)
        float S[4][4];
#pragma unroll
        for (int i = 0; i < 4; i++)
#pragma unroll
            for (int j = 0; j < 4; j++) S[i][j] = 0.0f;

#pragma unroll 8
        for (int d = 0; d < 64; d++) {
            float a0 = Qt[d * SMPAD + ti + 0];
            float a1 = Qt[d * SMPAD + ti + 1];
            float a2 = Qt[d * SMPAD + ti + 2];
            float a3 = Qt[d * SMPAD + ti + 3];
            float b0 = Kt[d * SMPAD + tj + 0];
            float b1 = Kt[d * SMPAD + tj + 1];
            float b2 = Kt[d * SMPAD + tj + 2];
            float b3 = Kt[d * SMPAD + tj + 3];
            S[0][0] = fmaf(a0, b0, S[0][0]); S[0][1] = fmaf(a0, b1, S[0][1]);
            S[0][2] = fmaf(a0, b2, S[0][2]); S[0][3] = fmaf(a0, b3, S[0][3]);
            S[1][0] = fmaf(a1, b0, S[1][0]); S[1][1] = fmaf(a1, b1, S[1][1]);
            S[1][2] = fmaf(a1, b2, S[1][2]); S[1][3] = fmaf(a1, b3, S[1][3]);
            S[2][0] = fmaf(a2, b0, S[2][0]); S[2][1] = fmaf(a2, b1, S[2][1]);
            S[2][2] = fmaf(a2, b2, S[2][2]); S[2][3] = fmaf(a2, b3, S[2][3]);
            S[3][0] = fmaf(a3, b0, S[3][0]); S[3][1] = fmaf(a3, b1, S[3][1]);
            S[3][2] = fmaf(a3, b2, S[3][2]); S[3][3] = fmaf(a3, b3, S[3][3]);
        }

        // scale + causal mask, write transposed into Ss[j][i]
#pragma unroll
        for (int jj = 0; jj < 4; jj++)
#pragma unroll
            for (int ii = 0; ii < 4; ii++) {
                float s = S[ii][jj] * scale;
                if (kt * 64 + tj + jj > qt * 64 + ti + ii) s = -1e30f;
                Ss[(tj + jj) * SMPAD + ti + ii] = s;
            }
        __syncthreads();

        // Online softmax row update (one thread per row)
        if (tid < 64) {
            float mold = m_sh[tid];
            float mx = mold;
#pragma unroll 8
            for (int j = 0; j < 64; j++) mx = fmaxf(mx, Ss[j * SMPAD + tid]);
            float sum = 0.0f;
#pragma unroll 8
            for (int j = 0; j < 64; j++) {
                float p = __expf(Ss[j * SMPAD + tid] - mx);
                Ss[j * SMPAD + tid] = p;
                sum += p;
            }
            float alpha = __expf(mold - mx);
            m_sh[tid]  = mx;
            l_sh[tid]  = l_sh[tid] * alpha + sum;
            al_sh[tid] = alpha;
        }
        __syncthreads();

        // Rescale O, then O += P @ V (rows ti.., d-cols tj..)
        float a0 = al_sh[ti + 0], a1 = al_sh[ti + 1];
        float a2 = al_sh[ti + 2], a3 = al_sh[ti + 3];
#pragma unroll
        for (int dd = 0; dd < 4; dd++) {
            O[0][dd] *= a0; O[1][dd] *= a1; O[2][dd] *= a2; O[3][dd] *= a3;
        }
#pragma unroll 8
        for (int j = 0; j < 64; j++) {
            float p0 = Ss[j * SMPAD + ti + 0];
            float p1 = Ss[j * SMPAD + ti + 1];
            float p2 = Ss[j * SMPAD + ti + 2];
            float p3 = Ss[j * SMPAD + ti + 3];
            float v0 = Vs[j * SMPAD + tj + 0];
            float v1 = Vs[j * SMPAD + tj + 1];
            float v2 = Vs[j * SMPAD + tj + 2];
            float v3 = Vs[j * SMPAD + tj + 3];
            O[0][0] = fmaf(p0, v0, O[0][0]); O[0][1] = fmaf(p0, v1, O[0][1]);
            O[0][2] = fmaf(p0, v2, O[0][2]); O[0][3] = fmaf(p0, v3, O[0][3]);
            O[1][0] = fmaf(p1, v0, O[1][0]); O[1][1] = fmaf(p1, v1, O[1][1]);
            O[1][2] = fmaf(p1, v2, O[1][2]); O[1][3] = fmaf(p1, v3, O[1][3]);
            O[2][0] = fmaf(p2, v0, O[2][0]); O[2][1] = fmaf(p2, v1, O[2][1]);
            O[2][2] = fmaf(p2, v2, O[2][2]); O[2][3] = fmaf(p2, v3, O[2][3]);
            O[3][0] = fmaf(p3, v0, O[3][0]); O[3][1] = fmaf(p3, v1, O[3][1]);
            O[3][2] = fmaf(p3, v2, O[3][2]); O[3][3] = fmaf(p3, v3, O[3][3]);
        }
    }

    // Final normalize + write y[b, l, h*64 + d]
    const int bb = bh >> 4;
    const int h  = bh & 15;
#pragma unroll
    for (int ii = 0; ii < 4; ii++) {
        float inv = 1.0f / l_sh[ti + ii];
        int row = qt * 64 + ti + ii;
        float* yo = y + (bb * L_ + row) * C_ + h * 64 + tj;
        yo[0] = O[ii][0] * inv;
        yo[1] = O[ii][1] * inv;
        yo[2] = O[ii][2] * inv;
        yo[3] = O[ii][3] * inv;
    }
}

// ---------------------------------------------------------------------------
extern "C" void kernel_launch(void* const* d_in, const int* in_sizes, int n_in,
                              void* d_out, int out_size)
{
    const float* x    = (const float*)d_in[0];
    const float* W    = (const float*)d_in[1];
    const float* bias = (const float*)d_in[2];
    float* y = (float*)d_out;

    dim3 g1(N_ / 128, M_ / 128);
    qkv_gemm_kernel<<<g1, 256>>>(x, W, bias);

    const size_t smem = (4 * 64 * SMPAD + 192) * sizeof(float);  // ~67 KB
    cudaFuncSetAttribute(attn_kernel,
                         cudaFuncAttributeMaxDynamicSharedMemorySize, (int)smem);
    dim3 g2(L_ / 64, B_ * H_);
    attn_kernel<<<g2, 256, smem>>>(y);
}

// round 2
// speedup vs baseline: 1.0117x; 1.0117x over previous
#include <cuda_runtime.h>
#include <math.h>

// Problem constants
#define B_ 4
#define L_ 2048
#define C_ 1024
#define H_ 16
#define D_ 64
#define M_ (B_ * L_)   // 8192
#define N_ (3 * C_)    // 3072
#define K_ (C_)        // 1024

// Scratch: Q/K/V in [B, H, L, D] layout (each 32 MB)
__device__ float g_q[B_ * H_ * L_ * D_];
__device__ float g_k[B_ * H_ * L_ * D_];
__device__ float g_v[B_ * H_ * L_ * D_];

// ---------------------------------------------------------------------------
// Kernel 1: qkv = x @ Wqkv + bias, scattered into [B,H,L,D] Q/K/V scratch.
// 128x128x16 tile, 256 threads, 8x8 register micro-tile per thread.
// ---------------------------------------------------------------------------
__global__ __launch_bounds__(256) void qkv_gemm_kernel(
    const float* __restrict__ x, const float* __restrict__ W,
    const float* __restrict__ bias)
{
    __shared__ float As[16][128];   // A^T tile: As[k][m]
    __shared__ float Bs[16][128];   // B tile:   Bs[k][n]

    const int tid = threadIdx.x;
    const int m0 = blockIdx.y * 128;
    const int n0 = blockIdx.x * 128;
    const int tm = (tid >> 4) << 3;   // 0..120 step 8
    const int tn = (tid & 15) << 3;   // 0..120 step 8

    float acc[8][8];
#pragma unroll
    for (int i = 0; i < 8; i++)
#pragma unroll
        for (int j = 0; j < 8; j++) acc[i][j] = 0.0f;

    for (int k0 = 0; k0 < K_; k0 += 16) {
#pragma unroll
        for (int it = 0; it < 2; it++) {
            int lin = tid + it * 256;            // 0..511
            // A: 128 rows x 16 cols, float4 along k
            int arow = lin >> 2;                 // 0..127
            int acol = (lin & 3) << 2;           // 0,4,8,12
            float4 a = *reinterpret_cast<const float4*>(
                &x[(m0 + arow) * K_ + k0 + acol]);
            As[acol + 0][arow] = a.x;
            As[acol + 1][arow] = a.y;
            As[acol + 2][arow] = a.z;
            As[acol + 3][arow] = a.w;
            // B: 16 rows x 128 cols, float4 along n
            int brow = lin >> 5;                 // 0..15
            int bcol = (lin & 31) << 2;          // 0..124
            *reinterpret_cast<float4*>(&Bs[brow][bcol]) =
                *reinterpret_cast<const float4*>(&W[(k0 + brow) * N_ + n0 + bcol]);
        }
        __syncthreads();

#pragma unroll
        for (int kk = 0; kk < 16; kk++) {
            float a[8], b[8];
            *reinterpret_cast<float4*>(&a[0]) = *reinterpret_cast<float4*>(&As[kk][tm]);
            *reinterpret_cast<float4*>(&a[4]) = *reinterpret_cast<float4*>(&As[kk][tm + 4]);
            *reinterpret_cast<float4*>(&b[0]) = *reinterpret_cast<float4*>(&Bs[kk][tn]);
            *reinterpret_cast<float4*>(&b[4]) = *reinterpret_cast<float4*>(&Bs[kk][tn + 4]);
#pragma unroll
            for (int i = 0; i < 8; i++)
#pragma unroll
                for (int j = 0; j < 8; j++)
                    acc[i][j] = fmaf(a[i], b[j], acc[i][j]);
        }
        __syncthreads();
    }

    // Epilogue: bias + scatter into [B,H,L,D]. All n in this block share q/k/v.
    const int which = n0 >> 10;  // 0=q, 1=k, 2=v (128 | 1024)
    float* dst = (which == 0) ? g_q : ((which == 1) ? g_k : g_v);
#pragma unroll
    for (int i = 0; i < 8; i++) {
        int m  = m0 + tm + i;
        int bb = m >> 11;            // / L_
        int l  = m & (L_ - 1);
#pragma unroll
        for (int j = 0; j < 8; j++) {
            int n = n0 + tn + j;
            int c = n & (C_ - 1);
            int h = c >> 6;
            int d = c & 63;
            dst[(((bb * H_ + h) * L_ + l) << 6) + d] = acc[i][j] + bias[n];
        }
    }
}

// ---------------------------------------------------------------------------
// Kernel 2: causal flash attention. One block per (b*h, 64-row query tile).
// 64-wide key tiles, online softmax, 4x4 micro-tiles, 256 threads.
// ---------------------------------------------------------------------------
#define SMPAD 65

__global__ __launch_bounds__(256) void attn_kernel(float* __restrict__ y)
{
    extern __shared__ float sm[];
    float* Qt   = sm;                    // [d][i]  64 x 65
    float* Kt   = Qt + 64 * SMPAD;       // [d][j]  64 x 65
    float* Vs   = Kt + 64 * SMPAD;       // [j][d]  64 x 65
    float* Ss   = Vs + 64 * SMPAD;       // [j][i]  64 x 65 (scores, then P)
    float* m_sh = Ss + 64 * SMPAD;       // [64] row max
    float* l_sh = m_sh + 64;             // [64] row sum
    float* al_sh = l_sh + 64;            // [64] rescale factor

    const int bh  = blockIdx.y;          // 0..63  (b*H + h)
    const int qt  = blockIdx.x;          // 0..31  query tile
    const int tid = threadIdx.x;
    const float scale = 0.125f;          // 1/sqrt(64)

    const float* qg = g_q + (bh * L_ + qt * 64) * 64;
    const float* kg = g_k + bh * L_ * 64;
    const float* vg = g_v + bh * L_ * 64;

    // Load Q tile transposed (d-major)
    for (int idx = tid; idx < 4096; idx += 256) {
        int r = idx >> 6, d = idx & 63;
        Qt[d * SMPAD + r] = qg[idx];
    }
    if (tid < 64) { m_sh[tid] = -1e30f; l_sh[tid] = 0.0f; }

    const int ti = (tid >> 4) << 2;      // query rows  [ti, ti+4)
    const int tj = (tid & 15) << 2;      // key cols / d cols [tj, tj+4)

    float O[4][4];
#pragma unroll
    for (int i = 0; i < 4; i++)
#pragma unroll
        for (int j = 0; j < 4; j++) O[i][j] = 0.0f;

    for (int kt = 0; kt <= qt; kt++) {
        __syncthreads();   // protect Kt/Vs/Ss from previous iteration's readers
        for (int idx = tid; idx < 4096; idx += 256) {
            int r = idx >> 6, d = idx & 63;
            float kv = kg[kt * 4096 + idx];
            Kt[d * SMPAD + r] = kv;
            Vs[r * SMPAD + d] = vg[kt * 4096 + idx];
        }
        __syncthreads();

        // S = Q K^T (4x4 micro-tile per thread)
        float S[4][4];
#pragma unroll
        for (int i = 0; i < 4; i++)
#pragma unroll
            for (int j = 0; j < 4; j++) S[i][j] = 0.0f;

#pragma unroll 8
        for (int d = 0; d < 64; d++) {
            float a0 = Qt[d * SMPAD + ti + 0];
            float a1 = Qt[d * SMPAD + ti + 1];
            float a2 = Qt[d * SMPAD + ti + 2];
            float a3 = Qt[d * SMPAD + ti + 3];
            float b0 = Kt[d * SMPAD + tj + 0];
            float b1 = Kt[d * SMPAD + tj + 1];
            float b2 = Kt[d * SMPAD + tj + 2];
            float b3 = Kt[d * SMPAD + tj + 3];
            S[0][0] = fmaf(a0, b0, S[0][0]); S[0][1] = fmaf(a0, b1, S[0][1]);
            S[0][2] = fmaf(a0, b2, S[0][2]); S[0][3] = fmaf(a0, b3, S[0][3]);
            S[1][0] = fmaf(a1, b0, S[1][0]); S[1][1] = fmaf(a1, b1, S[1][1]);
            S[1][2] = fmaf(a1, b2, S[1][2]); S[1][3] = fmaf(a1, b3, S[1][3]);
            S[2][0] = fmaf(a2, b0, S[2][0]); S[2][1] = fmaf(a2, b1, S[2][1]);
            S[2][2] = fmaf(a2, b2, S[2][2]); S[2][3] = fmaf(a2, b3, S[2][3]);
            S[3][0] = fmaf(a3, b0, S[3][0]); S[3][1] = fmaf(a3, b1, S[3][1]);
            S[3][2] = fmaf(a3, b2, S[3][2]); S[3][3] = fmaf(a3, b3, S[3][3]);
        }

        // scale + causal mask, write transposed into Ss[j][i]
#pragma unroll
        for (int jj = 0; jj < 4; jj++)
#pragma unroll
            for (int ii = 0; ii < 4; ii++) {
                float s = S[ii][jj] * scale;
                if (kt * 64 + tj + jj > qt * 64 + ti + ii) s = -1e30f;
                Ss[(tj + jj) * SMPAD + ti + ii] = s;
            }
        __syncthreads();

        // Online softmax row update (one thread per row)
        if (tid < 64) {
            float mold = m_sh[tid];
            float mx = mold;
#pragma unroll 8
            for (int j = 0; j < 64; j++) mx = fmaxf(mx, Ss[j * SMPAD + tid]);
            float sum = 0.0f;
#pragma unroll 8
            for (int j = 0; j < 64; j++) {
                float p = __expf(Ss[j * SMPAD + tid] - mx);
                Ss[j * SMPAD + tid] = p;
                sum += p;
            }
            float alpha = __expf(mold - mx);
            m_sh[tid]  = mx;
            l_sh[tid]  = l_sh[tid] * alpha + sum;
            al_sh[tid] = alpha;
        }
        __syncthreads();

        // Rescale O, then O += P @ V (rows ti.., d-cols tj..)
        float a0 = al_sh[ti + 0], a1 = al_sh[ti + 1];
        float a2 = al_sh[ti + 2], a3 = al_sh[ti + 3];
#pragma unroll
        for (int dd = 0; dd < 4; dd++) {
            O[0][dd] *= a0; O[1][dd] *= a1; O[2][dd] *= a2; O[3][dd] *= a3;
        }
#pragma unroll 8
        for (int j = 0; j < 64; j++) {
            float p0 = Ss[j * SMPAD + ti + 0];
            float p1 = Ss[j * SMPAD + ti + 1];
            float p2 = Ss[j * SMPAD + ti + 2];
            float p3 = Ss[j * SMPAD + ti + 3];
            float v0 = Vs[j * SMPAD + tj + 0];
            float v1 = Vs[j * SMPAD + tj + 1];
            float v2 = Vs[j * SMPAD + tj + 2];
            float v3 = Vs[j * SMPAD + tj + 3];
            O[0][0] = fmaf(p0, v0, O[0][0]); O[0][1] = fmaf(p0, v1, O[0][1]);
            O[0][2] = fmaf(p0, v2, O[0][2]); O[0][3] = fmaf(p0, v3, O[0][3]);
            O[1][0] = fmaf(p1, v0, O[1][0]); O[1][1] = fmaf(p1, v1, O[1][1]);
            O[1][2] = fmaf(p1, v2, O[1][2]); O[1][3] = fmaf(p1, v3, O[1][3]);
            O[2][0] = fmaf(p2, v0, O[2][0]); O[2][1] = fmaf(p2, v1, O[2][1]);
            O[2][2] = fmaf(p2, v2, O[2][2]); O[2][3] = fmaf(p2, v3, O[2][3]);
            O[3][0] = fmaf(p3, v0, O[3][0]); O[3][1] = fmaf(p3, v1, O[3][1]);
            O[3][2] = fmaf(p3, v2, O[3][2]); O[3][3] = fmaf(p3, v3, O[3][3]);
        }
    }

    // Final normalize + write y[b, l, h*64 + d]
    const int bb = bh >> 4;
    const int h  = bh & 15;
#pragma unroll
    for (int ii = 0; ii < 4; ii++) {
        float inv = 1.0f / l_sh[ti + ii];
        int row = qt * 64 + ti + ii;
        float* yo = y + (bb * L_ + row) * C_ + h * 64 + tj;
        yo[0] = O[ii][0] * inv;
        yo[1] = O[ii][1] * inv;
        yo[2] = O[ii][2] * inv;
        yo[3] = O[ii][3] * inv;
    }
}

// ---------------------------------------------------------------------------
extern "C" void kernel_launch(void* const* d_in, const int* in_sizes, int n_in,
                              void* d_out, int out_size)
{
    const float* x    = (const float*)d_in[0];
    const float* W    = (const float*)d_in[1];
    const float* bias = (const float*)d_in[2];
    float* y = (float*)d_out;

    dim3 g1(N_ / 128, M_ / 128);
    qkv_gemm_kernel<<<g1, 256>>>(x, W, bias);

    const size_t smem = (4 * 64 * SMPAD + 192) * sizeof(float);  // ~67 KB
    cudaFuncSetAttribute(attn_kernel,
                         cudaFuncAttributeMaxDynamicSharedMemorySize, (int)smem);
    dim3 g2(L_ / 64, B_ * H_);
    attn_kernel<<<g2, 256, smem>>>(y);
}